// round 9
// baseline (speedup 1.0000x reference)
#include <cuda_runtime.h>
#include <cuda_bf16.h>
#include <cstddef>

// Problem constants (fixed by reference)
#define NNODES 100000
#define D      256
#define BATCH  1024
#define S0     25
#define S1     10
#define N1     (BATCH * (1 + S1))   // 11264
#define KDIM   512                  // 2*D
#define BN     256                  // output dim (= D), full N per block

typedef unsigned long long ull;

// Scratch (device global; no allocation allowed)
__device__ float g_h1[(size_t)N1 * D];         // layer-1 output : 11264 x 256

// ---- packed fp32x2 helpers (Blackwell sm_103a; ptxas never auto-fuses) ----
__device__ __forceinline__ ull pack_dup_f32(float x) {
    ull r;
    asm("mov.b64 %0, {%1, %1};" : "=l"(r) : "f"(x));
    return r;
}
__device__ __forceinline__ void fma_f32x2(ull& d, ull a, ull b) {
    asm("fma.rn.f32x2 %0, %1, %2, %0;" : "+l"(d) : "l"(a), "l"(b));
}
__device__ __forceinline__ float2 unpack_f32x2(ull v) {
    float2 f;
    asm("mov.b64 {%0, %1}, %2;" : "=f"(f.x), "=f"(f.y) : "l"(v));
    return f;
}

// ---------------------------------------------------------------------------
// Fully fused layer kernel: gather + mean-agg + GEMM + bias + ReLU + L2 norm.
//
//   For each of its BM rows i (global row = rowBase+r):
//     x = [ feat[self(i)] | mean_j feat[neigh(i,j)] ]   (built in smem)
//   C[i][n] = relu( sum_k x[k] * W[n][k] + bias[n] ), then row L2-normalized.
//
// MODE 0 (layer 1): src = features; self = nodes2[i] (i<B) else neigh2[i-B];
//                   neighbors = neigh1[i][0..S0).
// MODE 1 (layer 2): src = h1; self = row i; neighbors = rows B + i*S1 + j.
//
// A-tile (BM x 512) resides in smem for the whole K loop. W (256 x 512,
// A @ W^T) is double-buffered in smem with register prefetch.
// 256 threads = 8 (ty: row groups of TM) x 32 (tx: col groups of 8).
// Mainloop uses packed fp32x2 FMAs (2 fp32 FMA per fma-pipe issue).
// ---------------------------------------------------------------------------
template<int BM, int TM, int MODE>
__global__ void __launch_bounds__(256) fused_layer_kernel(
    const float* __restrict__ src,     // features (MODE 0) or h1 (MODE 1)
    const float* __restrict__ W,
    const float* __restrict__ bias,
    const int*   __restrict__ nodes2,  // MODE 0 only
    const int*   __restrict__ neigh2,  // MODE 0 only
    const int*   __restrict__ neigh1,  // MODE 0 only
    float*       __restrict__ C)
{
    constexpr int BK  = 32;
    constexpr int NIT = KDIM / BK;           // 16 iterations
    constexpr int WL  = (BN * BK / 4) / 256; // 8 per-thread W float4 loads
    constexpr int NS  = (MODE == 0) ? S0 : S1;

    extern __shared__ float smem[];
    float* Xs    = smem;                       // BM * KDIM  (A tile, full K)
    float* WsBuf = smem + BM * KDIM;           // 2 * BK * BN
    float* s_inv = WsBuf + 2 * BK * BN;        // BM
    int*   s_idx = (int*)(s_inv + BM);         // MODE 0: BM self + BM*S0 nbrs

    const int tid = threadIdx.x;
    const int tx  = tid & 31;      // col group: cols [tx*8, tx*8+8)
    const int ty  = tid >> 5;      // row group: rows [ty*TM, ty*TM+TM)
    const int rowBase = blockIdx.x * BM;

    // ---- index load (MODE 0) ----
    if (MODE == 0) {
        if (tid < BM) {
            const int i = rowBase + tid;
            s_idx[tid] = (i < BATCH) ? nodes2[i] : neigh2[i - BATCH];
        }
        for (int q = tid; q < BM * S0; q += 256) {
            const int r = q / S0;
            const int s = q % S0;
            s_idx[BM + q] = neigh1[(rowBase + r) * S0 + s];
        }
        __syncthreads();
    }

    // ---- gather + mean-agg: build A tile in smem ----
    // thread t owns feature column t (t in [0,256)) for every row.
    {
        const int t = tid;
#pragma unroll 2
        for (int r = 0; r < BM; r++) {
            int selfIdx;
            if (MODE == 0) selfIdx = s_idx[r];
            else           selfIdx = rowBase + r;
            const float sv = __ldg(src + (size_t)selfIdx * D + t);
            float sum = 0.0f;
#pragma unroll 5
            for (int j = 0; j < NS; j++) {
                int nb;
                if (MODE == 0) nb = s_idx[BM + r * S0 + j];
                else           nb = BATCH + (rowBase + r) * S1 + j;
                sum += __ldg(src + (size_t)nb * D + t);
            }
            Xs[r * KDIM + t]     = sv;
            Xs[r * KDIM + D + t] = sum * (1.0f / (float)NS);
        }
    }

    // ---- W prologue: tile 0 -> buffer 0 ----
    float4 wR[WL];
#pragma unroll
    for (int i = 0; i < WL; i++) {
        const int q = tid + 256 * i;
        wR[i] = *(const float4*)(W + (size_t)(q >> 3) * KDIM + ((q & 7) * 4));
    }
#pragma unroll
    for (int i = 0; i < WL; i++) {
        const int q  = tid + 256 * i;
        const int j  = q >> 3;
        const int kq = (q & 7) * 4;
        WsBuf[(kq + 0) * BN + j] = wR[i].x;
        WsBuf[(kq + 1) * BN + j] = wR[i].y;
        WsBuf[(kq + 2) * BN + j] = wR[i].z;
        WsBuf[(kq + 3) * BN + j] = wR[i].w;
    }
    __syncthreads();   // A tile + W tile 0 visible to all

    // packed accumulators: acc2[r][j] = cols (tx*8 + 2j, tx*8 + 2j + 1)
    ull acc2[TM][4];
#pragma unroll
    for (int r = 0; r < TM; r++)
#pragma unroll
        for (int j = 0; j < 4; j++) acc2[r][j] = 0ull;

    // ---- mainloop (rolled: code stays in L1.5 I$) ----
    const float* WsC = WsBuf;
    float*       WsN = WsBuf + BK * BN;

#pragma unroll 1
    for (int it = 0; it < NIT; it++) {
        const bool has_next = (it + 1 < NIT);
        // prefetch next W tile into registers (LDGs overlap FMAs below)
        if (has_next) {
            const int k0 = (it + 1) * BK;
#pragma unroll
            for (int i = 0; i < WL; i++) {
                const int q = tid + 256 * i;
                wR[i] = *(const float4*)(W + (size_t)(q >> 3) * KDIM + k0 + ((q & 7) * 4));
            }
        }

        const int kbase = it * BK;
#pragma unroll
        for (int kk = 0; kk < BK / 4; kk++) {
            // A fragments: float4 (4 consecutive k) per row, broadcast LDS.128
            float4 av[TM];
#pragma unroll
            for (int r = 0; r < TM; r++)
                av[r] = *(const float4*)&Xs[(ty * TM + r) * KDIM + kbase + kk * 4];
#pragma unroll
            for (int j4 = 0; j4 < 4; j4++) {
                const int k = kk * 4 + j4;
                const ulonglong2* wp = (const ulonglong2*)&WsC[k * BN + tx * 8];
                ulonglong2 wlo = wp[0];
                ulonglong2 whi = wp[1];
                ull w2[4] = { wlo.x, wlo.y, whi.x, whi.y };
#pragma unroll
                for (int r = 0; r < TM; r++) {
                    const float a = (j4 == 0) ? av[r].x :
                                    (j4 == 1) ? av[r].y :
                                    (j4 == 2) ? av[r].z : av[r].w;
                    const ull ad = pack_dup_f32(a);
#pragma unroll
                    for (int j = 0; j < 4; j++)
                        fma_f32x2(acc2[r][j], ad, w2[j]);
                }
            }
        }

        // store prefetched W into alternate buffer; single sync; swap
        if (has_next) {
#pragma unroll
            for (int i = 0; i < WL; i++) {
                const int q  = tid + 256 * i;
                const int j  = q >> 3;
                const int kq = (q & 7) * 4;
                WsN[(kq + 0) * BN + j] = wR[i].x;
                WsN[(kq + 1) * BN + j] = wR[i].y;
                WsN[(kq + 2) * BN + j] = wR[i].z;
                WsN[(kq + 3) * BN + j] = wR[i].w;
            }
            __syncthreads();
            float* tmp = (float*)WsC; WsC = WsN; WsN = tmp;
        }
    }

    // ---- epilogue: unpack + bias + relu + row sumsq + L2 normalize ----
    float acc[TM][8];
#pragma unroll
    for (int r = 0; r < TM; r++)
#pragma unroll
        for (int j = 0; j < 4; j++) {
            float2 p = unpack_f32x2(acc2[r][j]);
            acc[r][2 * j]     = p.x;
            acc[r][2 * j + 1] = p.y;
        }

    float bv[8];
    {
        float4 ba = *(const float4*)(bias + tx * 8);
        float4 bb = *(const float4*)(bias + tx * 8 + 4);
        bv[0] = ba.x; bv[1] = ba.y; bv[2] = ba.z; bv[3] = ba.w;
        bv[4] = bb.x; bv[5] = bb.y; bv[6] = bb.z; bv[7] = bb.w;
    }
    float sq[TM];
#pragma unroll
    for (int r = 0; r < TM; r++) {
        sq[r] = 0.0f;
#pragma unroll
        for (int u = 0; u < 8; u++) {
            float v = acc[r][u] + bv[u];
            v = fmaxf(v, 0.0f);
            acc[r][u] = v;
            sq[r] = fmaf(v, v, sq[r]);
        }
    }
    // warp (fixed ty) spans all 256 columns -> shuffle reduce over 32 lanes
#pragma unroll
    for (int r = 0; r < TM; r++) {
#pragma unroll
        for (int o = 16; o > 0; o >>= 1)
            sq[r] += __shfl_xor_sync(0xffffffffu, sq[r], o);
    }
    if (tx == 0) {
#pragma unroll
        for (int r = 0; r < TM; r++)
            s_inv[ty * TM + r] = (sq[r] > 0.0f) ? rsqrtf(sq[r]) : 1.0f;
    }
    __syncthreads();

#pragma unroll
    for (int r = 0; r < TM; r++) {
        const float inv = s_inv[ty * TM + r];
        float4 o1 = make_float4(acc[r][0] * inv, acc[r][1] * inv,
                                acc[r][2] * inv, acc[r][3] * inv);
        float4 o2 = make_float4(acc[r][4] * inv, acc[r][5] * inv,
                                acc[r][6] * inv, acc[r][7] * inv);
        float* crow = C + (size_t)(rowBase + ty * TM + r) * BN + tx * 8;
        *(float4*)(crow)     = o1;
        *(float4*)(crow + 4) = o2;
    }
}

// ---------------------------------------------------------------------------
extern "C" void kernel_launch(void* const* d_in, const int* in_sizes, int n_in,
                              void* d_out, int out_size)
{
    const float* features = (const float*)d_in[0];
    const float* W0       = (const float*)d_in[1];
    const float* b0       = (const float*)d_in[2];
    const float* W1       = (const float*)d_in[3];
    const float* b1       = (const float*)d_in[4];
    const int*   nodes2   = (const int*)d_in[5];
    const int*   neigh2   = (const int*)d_in[6];
    const int*   neigh1   = (const int*)d_in[7];
    float*       out      = (float*)d_out;

    void* ph1;
    cudaGetSymbolAddress(&ph1, g_h1);
    float* h1 = (float*)ph1;

    // smem: A tile (BM*512) + W double buffer (2*32*256) + s_inv (BM)
    //       + MODE-0 index area (BM*(S0+1) ints)
    constexpr int BM1 = 32, TM1 = 4;
    constexpr int BM2 = 8,  TM2 = 1;
    size_t smem1 = (size_t)(BM1 * KDIM + 2 * 32 * BN + BM1) * sizeof(float)
                 + (size_t)(BM1 * (S0 + 1)) * sizeof(int);     // ~134.5 KB
    size_t smem2 = (size_t)(BM2 * KDIM + 2 * 32 * BN + BM2) * sizeof(float); // ~80 KB

    // Unconditional (no static guards per harness rules): deterministic,
    // host-side, not a stream op -> capture-safe.
    cudaFuncSetAttribute(fused_layer_kernel<BM1, TM1, 0>,
                         cudaFuncAttributeMaxDynamicSharedMemorySize, (int)smem1);
    cudaFuncSetAttribute(fused_layer_kernel<BM2, TM2, 1>,
                         cudaFuncAttributeMaxDynamicSharedMemorySize, (int)smem2);

    // Layer 1: gather+agg+GEMM+relu+norm -> h1 (11264 x 256), 352 blocks
    fused_layer_kernel<BM1, TM1, 0><<<N1 / BM1, 256, smem1>>>(
        features, W0, b0, nodes2, neigh2, neigh1, h1);

    // Layer 2: gather+agg+GEMM+relu+norm -> out (1024 x 256), 128 blocks
    fused_layer_kernel<BM2, TM2, 1><<<BATCH / BM2, 256, smem2>>>(
        h1, W1, b1, nullptr, nullptr, nullptr, out);
}

// round 17
// speedup vs baseline: 1.7612x; 1.7612x over previous
#include <cuda_runtime.h>
#include <cuda_bf16.h>
#include <cstddef>

// Problem constants (fixed by reference)
#define NNODES 100000
#define D      256
#define BATCH  1024
#define S0     25
#define S1     10
#define N1     (BATCH * (1 + S1))   // 11264
#define KDIM   512                  // 2*D
#define BN     256                  // output dim (= D), full N per block

typedef unsigned long long ull;

// Scratch (device global; no allocation allowed)
__device__ float g_h1[(size_t)N1 * D];         // layer-1 output : 11264 x 256

// ---- packed fp32x2 helpers (Blackwell sm_103a; ptxas never auto-fuses) ----
__device__ __forceinline__ ull pack_dup_f32(float x) {
    ull r;
    asm("mov.b64 %0, {%1, %1};" : "=l"(r) : "f"(x));
    return r;
}
__device__ __forceinline__ void fma_f32x2(ull& d, ull a, ull b) {
    asm("fma.rn.f32x2 %0, %1, %2, %0;" : "+l"(d) : "l"(a), "l"(b));
}
__device__ __forceinline__ float2 unpack_f32x2(ull v) {
    float2 f;
    asm("mov.b64 {%0, %1}, %2;" : "=f"(f.x), "=f"(f.y) : "l"(v));
    return f;
}

// ---------------------------------------------------------------------------
// Fully fused layer kernel: gather + mean-agg + GEMM + bias + ReLU + L2 norm.
//
// MODE 0 (layer 1): src = features; self = nodes2[i] (i<B) else neigh2[i-B];
//                   neighbors = neigh1[i][0..S0).
// MODE 1 (layer 2): src = h1; self = row i; neighbors = rows B + i*S1 + j.
//
// NT threads = (NT/32) ty row-groups x 32 tx lanes (8 cols each = 256 cols).
// A-tile (BM x 512) built in smem via float4 gathers (indices read directly
// via uniform __ldg broadcast -- no smem staging, no extra barrier).
// W tile 0 LDGs issued FIRST so they fly under the gather chain.
// W double-buffered (BK=16) with register prefetch. fp32x2 packed FMAs.
// Small smem (~64 KB) -> 3 CTAs/SM on layer 1 for latency hiding
// (R9 profile: issue=8.1% at 8 warps/SM = starvation).
// ---------------------------------------------------------------------------
template<int BM, int TM, int MODE, int NT, int BK>
__global__ void __launch_bounds__(NT) fused_layer_kernel(
    const float* __restrict__ src,     // features (MODE 0) or h1 (MODE 1)
    const float* __restrict__ W,
    const float* __restrict__ bias,
    const int*   __restrict__ nodes2,  // MODE 0 only
    const int*   __restrict__ neigh2,  // MODE 0 only
    const int*   __restrict__ neigh1,  // MODE 0 only
    float*       __restrict__ C)
{
    constexpr int NIT = KDIM / BK;          // K iterations
    constexpr int F4R = BK / 4;             // float4s per W row-chunk
    constexpr int WL  = (BN * F4R) / NT;    // per-thread W float4 loads
    constexpr int NS  = (MODE == 0) ? S0 : S1;
    constexpr int NWY = NT / 32;            // ty groups
    static_assert(NWY * TM == BM, "layout");

    extern __shared__ float smem[];
    float* Xs    = smem;                    // BM * KDIM (A tile, full K)
    float* WsBuf = smem + BM * KDIM;        // 2 * BK * BN

    const int tid = threadIdx.x;
    const int tx  = tid & 31;      // col group: cols [tx*8, tx*8+8)
    const int ty  = tid >> 5;      // row group: rows [ty*TM, ty*TM+TM)
    const int rowBase = blockIdx.x * BM;

    // ---- W tile 0 LDGs first: in flight underneath the whole gather ----
    float4 wR[WL];
#pragma unroll
    for (int i = 0; i < WL; i++) {
        const int q = tid + NT * i;
        wR[i] = *(const float4*)(W + (size_t)(q / F4R) * KDIM + ((q % F4R) * 4));
    }

    // ---- gather + mean-agg via float4 loads: build A tile in smem ----
    // 64 threads cover D=256 floats as 64 float4s; NT/64 row groups.
    // Indices are warp-uniform within a row group -> __ldg broadcast.
    {
        constexpr int RG  = NT / 64;   // parallel row groups
        constexpr int RPT = BM / RG;   // rows per thread
        const int c4 = tid & 63;       // float4 column
        const int rg = tid >> 6;       // row group
        const float invn = 1.0f / (float)NS;
#pragma unroll
        for (int rr = 0; rr < RPT; rr++) {
            const int r = rg + rr * RG;
            const int i = rowBase + r;
            int selfIdx;
            if (MODE == 0)
                selfIdx = (i < BATCH) ? __ldg(nodes2 + i) : __ldg(neigh2 + (i - BATCH));
            else
                selfIdx = i;
            float4 sv = __ldg((const float4*)(src + (size_t)selfIdx * D) + c4);
            float4 sum = make_float4(0.f, 0.f, 0.f, 0.f);
#pragma unroll
            for (int j = 0; j < NS; j++) {
                int nb;
                if (MODE == 0) nb = __ldg(neigh1 + i * S0 + j);
                else           nb = BATCH + i * S1 + j;
                float4 v = __ldg((const float4*)(src + (size_t)nb * D) + c4);
                sum.x += v.x; sum.y += v.y; sum.z += v.z; sum.w += v.w;
            }
            *(float4*)&Xs[r * KDIM + c4 * 4] = sv;
            *(float4*)&Xs[r * KDIM + D + c4 * 4] =
                make_float4(sum.x * invn, sum.y * invn, sum.z * invn, sum.w * invn);
        }
    }

    // ---- W prologue: tile 0 -> buffer 0 ----
#pragma unroll
    for (int i = 0; i < WL; i++) {
        const int q  = tid + NT * i;
        const int j  = q / F4R;
        const int kq = (q % F4R) * 4;
        WsBuf[(kq + 0) * BN + j] = wR[i].x;
        WsBuf[(kq + 1) * BN + j] = wR[i].y;
        WsBuf[(kq + 2) * BN + j] = wR[i].z;
        WsBuf[(kq + 3) * BN + j] = wR[i].w;
    }
    __syncthreads();   // A tile + W tile 0 visible

    // packed accumulators: acc2[r][j] = cols (tx*8 + 2j, tx*8 + 2j + 1)
    ull acc2[TM][4];
#pragma unroll
    for (int r = 0; r < TM; r++)
#pragma unroll
        for (int j = 0; j < 4; j++) acc2[r][j] = 0ull;

    // ---- mainloop (rolled: code stays in L1.5 I$) ----
    const float* WsC = WsBuf;
    float*       WsN = WsBuf + BK * BN;

#pragma unroll 1
    for (int it = 0; it < NIT; it++) {
        const bool has_next = (it + 1 < NIT);
        if (has_next) {   // prefetch next W tile into registers
            const int k0 = (it + 1) * BK;
#pragma unroll
            for (int i = 0; i < WL; i++) {
                const int q = tid + NT * i;
                wR[i] = *(const float4*)(W + (size_t)(q / F4R) * KDIM + k0 + ((q % F4R) * 4));
            }
        }

        const int kbase = it * BK;
#pragma unroll
        for (int kk = 0; kk < BK / 4; kk++) {
            float4 av[TM];
#pragma unroll
            for (int r = 0; r < TM; r++)
                av[r] = *(const float4*)&Xs[(ty * TM + r) * KDIM + kbase + kk * 4];
#pragma unroll
            for (int j4 = 0; j4 < 4; j4++) {
                const int k = kk * 4 + j4;
                const ulonglong2* wp = (const ulonglong2*)&WsC[k * BN + tx * 8];
                ulonglong2 wlo = wp[0];
                ulonglong2 whi = wp[1];
                ull w2[4] = { wlo.x, wlo.y, whi.x, whi.y };
#pragma unroll
                for (int r = 0; r < TM; r++) {
                    const float a = (j4 == 0) ? av[r].x :
                                    (j4 == 1) ? av[r].y :
                                    (j4 == 2) ? av[r].z : av[r].w;
                    const ull ad = pack_dup_f32(a);
#pragma unroll
                    for (int j = 0; j < 4; j++)
                        fma_f32x2(acc2[r][j], ad, w2[j]);
                }
            }
        }

        if (has_next) {   // store prefetched W; single sync; swap
#pragma unroll
            for (int i = 0; i < WL; i++) {
                const int q  = tid + NT * i;
                const int j  = q / F4R;
                const int kq = (q % F4R) * 4;
                WsN[(kq + 0) * BN + j] = wR[i].x;
                WsN[(kq + 1) * BN + j] = wR[i].y;
                WsN[(kq + 2) * BN + j] = wR[i].z;
                WsN[(kq + 3) * BN + j] = wR[i].w;
            }
            __syncthreads();
            float* tmp = (float*)WsC; WsC = WsN; WsN = tmp;
        }
    }

    // ---- epilogue: unpack + bias + relu + row sumsq + L2 normalize ----
    // Butterfly reduce leaves the row sum in ALL lanes -> no smem, no sync.
    float acc[TM][8];
#pragma unroll
    for (int r = 0; r < TM; r++)
#pragma unroll
        for (int j = 0; j < 4; j++) {
            float2 p = unpack_f32x2(acc2[r][j]);
            acc[r][2 * j]     = p.x;
            acc[r][2 * j + 1] = p.y;
        }

    float bv[8];
    {
        float4 ba = *(const float4*)(bias + tx * 8);
        float4 bb = *(const float4*)(bias + tx * 8 + 4);
        bv[0] = ba.x; bv[1] = ba.y; bv[2] = ba.z; bv[3] = ba.w;
        bv[4] = bb.x; bv[5] = bb.y; bv[6] = bb.z; bv[7] = bb.w;
    }
#pragma unroll
    for (int r = 0; r < TM; r++) {
        float sq = 0.0f;
#pragma unroll
        for (int u = 0; u < 8; u++) {
            float v = acc[r][u] + bv[u];
            v = fmaxf(v, 0.0f);
            acc[r][u] = v;
            sq = fmaf(v, v, sq);
        }
#pragma unroll
        for (int o = 16; o > 0; o >>= 1)
            sq += __shfl_xor_sync(0xffffffffu, sq, o);
        const float inv = (sq > 0.0f) ? rsqrtf(sq) : 1.0f;
        float4 o1 = make_float4(acc[r][0] * inv, acc[r][1] * inv,
                                acc[r][2] * inv, acc[r][3] * inv);
        float4 o2 = make_float4(acc[r][4] * inv, acc[r][5] * inv,
                                acc[r][6] * inv, acc[r][7] * inv);
        float* crow = C + (size_t)(rowBase + ty * TM + r) * BN + tx * 8;
        *(float4*)(crow)     = o1;
        *(float4*)(crow + 4) = o2;
    }
}

// ---------------------------------------------------------------------------
extern "C" void kernel_launch(void* const* d_in, const int* in_sizes, int n_in,
                              void* d_out, int out_size)
{
    const float* features = (const float*)d_in[0];
    const float* W0       = (const float*)d_in[1];
    const float* b0       = (const float*)d_in[2];
    const float* W1       = (const float*)d_in[3];
    const float* b1       = (const float*)d_in[4];
    const int*   nodes2   = (const int*)d_in[5];
    const int*   neigh2   = (const int*)d_in[6];
    const int*   neigh1   = (const int*)d_in[7];
    float*       out      = (float*)d_out;

    void* ph1;
    cudaGetSymbolAddress(&ph1, g_h1);
    float* h1 = (float*)ph1;

    // Layer 1: BM=16, TM=2, 256 thr, BK=16, grid 704, 64 KB smem -> 3 CTAs/SM
    // Layer 2: BM=4,  TM=1, 128 thr, BK=16, grid 256, 40 KB smem -> multi-CTA
    constexpr int BM1 = 16, TM1 = 2, NT1 = 256, BK1 = 16;
    constexpr int BM2 = 4,  TM2 = 1, NT2 = 128, BK2 = 16;
    size_t smem1 = (size_t)(BM1 * KDIM + 2 * BK1 * BN) * sizeof(float); // 64 KB
    size_t smem2 = (size_t)(BM2 * KDIM + 2 * BK2 * BN) * sizeof(float); // 40 KB

    cudaFuncSetAttribute(fused_layer_kernel<BM1, TM1, 0, NT1, BK1>,
                         cudaFuncAttributeMaxDynamicSharedMemorySize, (int)smem1);
    cudaFuncSetAttribute(fused_layer_kernel<BM2, TM2, 1, NT2, BK2>,
                         cudaFuncAttributeMaxDynamicSharedMemorySize, (int)smem2);

    // Layer 1: gather+agg+GEMM+relu+norm -> h1 (11264 x 256), 704 blocks
    fused_layer_kernel<BM1, TM1, 0, NT1, BK1><<<N1 / BM1, NT1, smem1>>>(
        features, W0, b0, nodes2, neigh2, neigh1, h1);

    // Layer 2: gather+agg+GEMM+relu+norm -> out (1024 x 256), 256 blocks
    fused_layer_kernel<BM2, TM2, 1, NT2, BK2><<<BATCH / BM2, NT2, smem2>>>(
        h1, W1, b1, nullptr, nullptr, nullptr, out);
}